// round 1
// baseline (speedup 1.0000x reference)
#include <cuda_runtime.h>
#include <cuda_bf16.h>
#include <math.h>

// Problem constants
#define BB 2
#define LL 4096
#define EE 256
#define HH 8
#define DD 32
#define NPAIR 16           // HEAD_DIM/2 rope pairs
#define BHL (BB*HH*LL)     // 65536 rows of head-dim vectors

typedef unsigned long long ull;

// ---------------- device scratch (no allocs allowed) ----------------
__device__ float g_qh[BB*HH*LL*DD];
__device__ float g_kh[BB*HH*LL*DD];
__device__ float g_vh[BB*HH*LL*DD];
__device__ float g_ao[BB*HH*LL*DD];
__device__ float g_cos[LL*NPAIR];
__device__ float g_sin[LL*NPAIR];

// ---------------- f32x2 packed helpers ----------------
__device__ __forceinline__ ull fma2(ull a, ull b, ull c) {
    ull d;
    asm("fma.rn.f32x2 %0, %1, %2, %3;" : "=l"(d) : "l"(a), "l"(b), "l"(c));
    return d;
}
__device__ __forceinline__ ull mul2(ull a, ull b) {
    ull d;
    asm("mul.rn.f32x2 %0, %1, %2;" : "=l"(d) : "l"(a), "l"(b));
    return d;
}
__device__ __forceinline__ ull pack2(float lo, float hi) {
    ull r;
    asm("mov.b64 %0, {%1, %2};" : "=l"(r) : "f"(lo), "f"(hi));
    return r;
}
__device__ __forceinline__ float2 unpack2(ull v) {
    float2 r;
    asm("mov.b64 {%0, %1}, %2;" : "=f"(r.x), "=f"(r.y) : "l"(v));
    return r;
}

// ---------------- rope table ----------------
__global__ void rope_table_kernel() {
    int idx = blockIdx.x * blockDim.x + threadIdx.x;  // < LL*NPAIR
    if (idx >= LL * NPAIR) return;
    int l = idx >> 4;
    int i = idx & 15;
    float t = (i < 8) ? (float)(l & 63) : (float)(l >> 6);
    int fi = i & 7;
    float freq = powf(10000.0f, -(4.0f * (float)fi) / 32.0f);
    float ang = t * freq;
    g_cos[idx] = cosf(ang);
    g_sin[idx] = sinf(ang);
}

// ---------------- projection GEMM ----------------
// C[M=8192, N=256] = A[M,256] @ W[N,256]^T + bias
// MODE 0: Q proj -> rope -> g_qh [B,H,L,D]
// MODE 1: K proj -> rope -> g_kh
// MODE 2: V proj ->        g_vh
// MODE 3: out proj, A gathered from g_ao [B,H,L,D], result -> d_out [B,L,E]
template <int MODE>
__global__ __launch_bounds__(256)
void gemm_proj(const float* __restrict__ A, const float* __restrict__ W,
               const float* __restrict__ bias, float* __restrict__ out) {
    __shared__ __align__(16) float As[16][68];
    __shared__ __align__(16) float Bs[16][68];

    const int t = threadIdx.x;
    const int m0 = blockIdx.y * 64;
    const int n0 = blockIdx.x * 64;
    const int lrow = t >> 2;      // 0..63
    const int seg = t & 3;        // 0..3
    const int tx = t & 15;        // 0..15 (N micro)
    const int ty = t >> 4;        // 0..15 (M micro)

    float acc[4][4];
#pragma unroll
    for (int i = 0; i < 4; i++)
#pragma unroll
        for (int j = 0; j < 4; j++) acc[i][j] = 0.0f;

    for (int kt = 0; kt < 256; kt += 16) {
        float4 a4;
        if (MODE != 3) {
            a4 = *(const float4*)(A + (m0 + lrow) * 256 + kt + seg * 4);
        } else {
            int m = m0 + lrow;
            int kk = kt + seg * 4;
            int b = m >> 12, l = m & 4095;
            int h = kk >> 5, d = kk & 31;
            a4 = *(const float4*)(g_ao + (((size_t)(b * HH + h) * LL) + l) * DD + d);
        }
        As[seg * 4 + 0][lrow] = a4.x;
        As[seg * 4 + 1][lrow] = a4.y;
        As[seg * 4 + 2][lrow] = a4.z;
        As[seg * 4 + 3][lrow] = a4.w;

        float4 b4 = *(const float4*)(W + (n0 + lrow) * 256 + kt + seg * 4);
        Bs[seg * 4 + 0][lrow] = b4.x;
        Bs[seg * 4 + 1][lrow] = b4.y;
        Bs[seg * 4 + 2][lrow] = b4.z;
        Bs[seg * 4 + 3][lrow] = b4.w;
        __syncthreads();

#pragma unroll
        for (int kk = 0; kk < 16; kk++) {
            float4 av = *(const float4*)&As[kk][ty * 4];
            float4 bv = *(const float4*)&Bs[kk][tx * 4];
            float a[4] = {av.x, av.y, av.z, av.w};
            float b[4] = {bv.x, bv.y, bv.z, bv.w};
#pragma unroll
            for (int i = 0; i < 4; i++)
#pragma unroll
                for (int j = 0; j < 4; j++) acc[i][j] += a[i] * b[j];
        }
        __syncthreads();
    }

    // epilogue
    float bvals[4];
#pragma unroll
    for (int j = 0; j < 4; j++) bvals[j] = bias[n0 + tx * 4 + j];

#pragma unroll
    for (int i = 0; i < 4; i++) {
        int m = m0 + ty * 4 + i;
        int b = m >> 12, l = m & 4095;
        if (MODE == 3) {
#pragma unroll
            for (int j = 0; j < 4; j++)
                out[(size_t)m * 256 + n0 + tx * 4 + j] = acc[i][j] + bvals[j];
        } else {
            int ncol = n0 + tx * 4;
#pragma unroll
            for (int pp = 0; pp < 2; pp++) {
                float real = acc[i][pp * 2 + 0] + bvals[pp * 2 + 0];
                float imag = acc[i][pp * 2 + 1] + bvals[pp * 2 + 1];
                int c = ncol + pp * 2;
                int h = c >> 5, d = c & 31;
                float out_r, out_i;
                if (MODE == 2) {
                    out_r = real;
                    out_i = imag;
                } else {
                    int p = d >> 1;
                    float cs = g_cos[l * NPAIR + p];
                    float sn = g_sin[l * NPAIR + p];
                    out_r = real * cs - imag * sn;
                    out_i = real * sn + imag * cs;
                }
                float* dst;
                if (MODE == 0) dst = g_qh;
                else if (MODE == 1) dst = g_kh;
                else dst = g_vh;
                dst += (((size_t)(b * HH + h) * LL) + l) * DD + d;
                dst[0] = out_r;
                dst[1] = out_i;
            }
        }
    }
}

// ---------------- flash attention ----------------
// grid (L/128, B*H), 128 threads; 1 query per thread; K/V tiles of 32 keys.
__global__ __launch_bounds__(128)
void attn_kernel() {
    __shared__ __align__(16) float Ks[32][32];
    __shared__ __align__(16) float Vs[32][32];

    const int bh = blockIdx.y;
    const int tid = threadIdx.x;
    const int qi = blockIdx.x * 128 + tid;

    const float* Qb = g_qh + (size_t)bh * LL * DD;
    const float* Kb = g_kh + (size_t)bh * LL * DD;
    const float* Vb = g_vh + (size_t)bh * LL * DD;

    // q into packed registers: 16 pairs
    ull qp[16];
    {
        const ulonglong2* qg = (const ulonglong2*)(Qb + (size_t)qi * DD);
#pragma unroll
        for (int tt = 0; tt < 8; tt++) {
            ulonglong2 v = qg[tt];
            qp[2 * tt + 0] = v.x;
            qp[2 * tt + 1] = v.y;
        }
    }

    ull acc2[16];
#pragma unroll
    for (int d = 0; d < 16; d++) acc2[d] = 0ULL;

    float mx = -3.0e38f;
    float lsum = 0.0f;
    const float scale = 0.17677669529663687f;  // 1/sqrt(32)

    for (int kt = 0; kt < LL; kt += 32) {
        // cooperative tile load: 256 float4 per tile, 128 threads -> 2 each
        {
            const float4* Kg = (const float4*)(Kb + (size_t)kt * DD);
            const float4* Vg = (const float4*)(Vb + (size_t)kt * DD);
            float4* Ksm = (float4*)Ks;
            float4* Vsm = (float4*)Vs;
            Ksm[tid] = Kg[tid];
            Ksm[tid + 128] = Kg[tid + 128];
            Vsm[tid] = Vg[tid];
            Vsm[tid + 128] = Vg[tid + 128];
        }
        __syncthreads();

        float s[32];
        const ulonglong2* Ku = (const ulonglong2*)Ks;
#pragma unroll
        for (int j = 0; j < 32; j++) {
            ull a0 = 0ULL, a1 = 0ULL;
#pragma unroll
            for (int tt = 0; tt < 8; tt++) {
                ulonglong2 kv = Ku[j * 8 + tt];
                a0 = fma2(qp[2 * tt + 0], kv.x, a0);
                a1 = fma2(qp[2 * tt + 1], kv.y, a1);
            }
            float2 f0 = unpack2(a0);
            float2 f1 = unpack2(a1);
            s[j] = (f0.x + f0.y + f1.x + f1.y) * scale;
        }

        float tmax = mx;
#pragma unroll
        for (int j = 0; j < 32; j++) tmax = fmaxf(tmax, s[j]);

        float corr = __expf(mx - tmax);
        mx = tmax;
        lsum *= corr;
        ull cor2 = pack2(corr, corr);
#pragma unroll
        for (int d = 0; d < 16; d++) acc2[d] = mul2(acc2[d], cor2);

        const ulonglong2* Vu = (const ulonglong2*)Vs;
#pragma unroll
        for (int j = 0; j < 32; j++) {
            float p = __expf(s[j] - mx);
            lsum += p;
            ull p2 = pack2(p, p);
#pragma unroll
            for (int tt = 0; tt < 8; tt++) {
                ulonglong2 vv = Vu[j * 8 + tt];
                acc2[2 * tt + 0] = fma2(p2, vv.x, acc2[2 * tt + 0]);
                acc2[2 * tt + 1] = fma2(p2, vv.y, acc2[2 * tt + 1]);
            }
        }
        __syncthreads();
    }

    float inv = 1.0f / lsum;
    float* outp = g_ao + (size_t)bh * LL * DD + (size_t)qi * DD;
#pragma unroll
    for (int d = 0; d < 16; d++) {
        float2 f = unpack2(acc2[d]);
        outp[2 * d + 0] = f.x * inv;
        outp[2 * d + 1] = f.y * inv;
    }
}

// ---------------- launcher ----------------
extern "C" void kernel_launch(void* const* d_in, const int* in_sizes, int n_in,
                              void* d_out, int out_size) {
    const float* q  = (const float*)d_in[0];
    const float* k  = (const float*)d_in[1];
    const float* v  = (const float*)d_in[2];
    const float* Wq = (const float*)d_in[3];
    const float* bq = (const float*)d_in[4];
    const float* Wk = (const float*)d_in[5];
    const float* bk = (const float*)d_in[6];
    const float* Wv = (const float*)d_in[7];
    const float* bv = (const float*)d_in[8];
    const float* Wo = (const float*)d_in[9];
    const float* bo = (const float*)d_in[10];
    float* out = (float*)d_out;

    rope_table_kernel<<<(LL * NPAIR + 255) / 256, 256>>>();

    dim3 gg(EE / 64, (BB * LL) / 64);  // (4, 128)
    gemm_proj<0><<<gg, 256>>>(q, Wq, bq, nullptr);
    gemm_proj<1><<<gg, 256>>>(k, Wk, bk, nullptr);
    gemm_proj<2><<<gg, 256>>>(v, Wv, bv, nullptr);

    attn_kernel<<<dim3(LL / 128, BB * HH), 128>>>();

    gemm_proj<3><<<gg, 256>>>(nullptr, Wo, bo, out);
}

// round 2
// speedup vs baseline: 3.4203x; 3.4203x over previous
#include <cuda_runtime.h>
#include <cuda_bf16.h>
#include <math.h>

// Problem constants
#define BB 2
#define LL 4096
#define EE 256
#define HH 8
#define DD 32
#define NPAIR 16
#define KT 64     // keys per attention tile
#define QT 128    // queries per attention CTA

typedef unsigned int uint32;

// ---------------- device scratch ----------------
__device__ float g_qh[BB*HH*LL*DD];
__device__ float g_kh[BB*HH*LL*DD];
__device__ float g_vh[BB*HH*LL*DD];
__device__ float g_ao[BB*HH*LL*DD];
__device__ float g_cos[LL*NPAIR];
__device__ float g_sin[LL*NPAIR];

// ---------------- helpers ----------------
__device__ __forceinline__ float tf32r(float x) {
    uint32 u;
    asm("cvt.rna.tf32.f32 %0, %1;" : "=r"(u) : "f"(x));
    return __uint_as_float(u);
}
__device__ __forceinline__ float ex2f(float x) {
    float r;
    asm("ex2.approx.f32 %0, %1;" : "=f"(r) : "f"(x));
    return r;
}
__device__ __forceinline__ void mma_tf32(float* d, const uint32* a, const uint32* b) {
    asm volatile(
        "mma.sync.aligned.m16n8k8.row.col.f32.tf32.tf32.f32 "
        "{%0,%1,%2,%3}, {%4,%5,%6,%7}, {%8,%9}, {%0,%1,%2,%3};"
        : "+f"(d[0]), "+f"(d[1]), "+f"(d[2]), "+f"(d[3])
        : "r"(a[0]), "r"(a[1]), "r"(a[2]), "r"(a[3]), "r"(b[0]), "r"(b[1]));
}

// ---------------- rope table ----------------
__global__ void rope_table_kernel() {
    int idx = blockIdx.x * blockDim.x + threadIdx.x;
    if (idx >= LL * NPAIR) return;
    int l = idx >> 4;
    int i = idx & 15;
    float t = (i < 8) ? (float)(l & 63) : (float)(l >> 6);
    int fi = i & 7;
    float freq = powf(10000.0f, -(4.0f * (float)fi) / 32.0f);
    float ang = t * freq;
    g_cos[idx] = cosf(ang);
    g_sin[idx] = sinf(ang);
}

// ---------------- projection GEMM ----------------
// C[M=8192, N=256] = A[M,256] @ W[N,256]^T + bias
// MODE 0: Q proj -> rope -> *scale*log2e -> tf32 round -> g_qh
// MODE 1: K proj -> rope -> tf32 round -> g_kh
// MODE 2: V proj -> tf32 round -> g_vh
// MODE 3: out proj from g_ao -> d_out
template <int MODE>
__global__ __launch_bounds__(256)
void gemm_proj(const float* __restrict__ A, const float* __restrict__ W,
               const float* __restrict__ bias, float* __restrict__ out) {
    __shared__ __align__(16) float As[16][68];
    __shared__ __align__(16) float Bs[16][68];

    const int t = threadIdx.x;
    const int m0 = blockIdx.y * 64;
    const int n0 = blockIdx.x * 64;
    const int lrow = t >> 2;
    const int seg = t & 3;
    const int tx = t & 15;
    const int ty = t >> 4;

    float acc[4][4];
#pragma unroll
    for (int i = 0; i < 4; i++)
#pragma unroll
        for (int j = 0; j < 4; j++) acc[i][j] = 0.0f;

    for (int kt = 0; kt < 256; kt += 16) {
        float4 a4;
        if (MODE != 3) {
            a4 = *(const float4*)(A + (m0 + lrow) * 256 + kt + seg * 4);
        } else {
            int m = m0 + lrow;
            int kk = kt + seg * 4;
            int b = m >> 12, l = m & 4095;
            int h = kk >> 5, d = kk & 31;
            a4 = *(const float4*)(g_ao + (((size_t)(b * HH + h) * LL) + l) * DD + d);
        }
        As[seg * 4 + 0][lrow] = a4.x;
        As[seg * 4 + 1][lrow] = a4.y;
        As[seg * 4 + 2][lrow] = a4.z;
        As[seg * 4 + 3][lrow] = a4.w;

        float4 b4 = *(const float4*)(W + (n0 + lrow) * 256 + kt + seg * 4);
        Bs[seg * 4 + 0][lrow] = b4.x;
        Bs[seg * 4 + 1][lrow] = b4.y;
        Bs[seg * 4 + 2][lrow] = b4.z;
        Bs[seg * 4 + 3][lrow] = b4.w;
        __syncthreads();

#pragma unroll
        for (int kk = 0; kk < 16; kk++) {
            float4 av = *(const float4*)&As[kk][ty * 4];
            float4 bv = *(const float4*)&Bs[kk][tx * 4];
            float a[4] = {av.x, av.y, av.z, av.w};
            float b[4] = {bv.x, bv.y, bv.z, bv.w};
#pragma unroll
            for (int i = 0; i < 4; i++)
#pragma unroll
                for (int j = 0; j < 4; j++) acc[i][j] += a[i] * b[j];
        }
        __syncthreads();
    }

    float bvals[4];
#pragma unroll
    for (int j = 0; j < 4; j++) bvals[j] = bias[n0 + tx * 4 + j];

    // scale*log2e folded into Q: (1/sqrt(32)) * log2(e)
    const float QS = 0.17677669529663687f * 1.4426950408889634f;

#pragma unroll
    for (int i = 0; i < 4; i++) {
        int m = m0 + ty * 4 + i;
        int b = m >> 12, l = m & 4095;
        if (MODE == 3) {
#pragma unroll
            for (int j = 0; j < 4; j++)
                out[(size_t)m * 256 + n0 + tx * 4 + j] = acc[i][j] + bvals[j];
        } else {
            int ncol = n0 + tx * 4;
#pragma unroll
            for (int pp = 0; pp < 2; pp++) {
                float real = acc[i][pp * 2 + 0] + bvals[pp * 2 + 0];
                float imag = acc[i][pp * 2 + 1] + bvals[pp * 2 + 1];
                int c = ncol + pp * 2;
                int h = c >> 5, d = c & 31;
                float out_r, out_i;
                if (MODE == 2) {
                    out_r = real;
                    out_i = imag;
                } else {
                    int p = d >> 1;
                    float cs = g_cos[l * NPAIR + p];
                    float sn = g_sin[l * NPAIR + p];
                    out_r = real * cs - imag * sn;
                    out_i = real * sn + imag * cs;
                }
                if (MODE == 0) { out_r *= QS; out_i *= QS; }
                out_r = tf32r(out_r);
                out_i = tf32r(out_i);
                float* dst;
                if (MODE == 0) dst = g_qh;
                else if (MODE == 1) dst = g_kh;
                else dst = g_vh;
                dst += (((size_t)(b * HH + h) * LL) + l) * DD + d;
                dst[0] = out_r;
                dst[1] = out_i;
            }
        }
    }
}

// ---------------- flash attention with tf32 mma.sync ----------------
// 4 warps (128 threads). Each CTA: 128 queries; warp handles 32 (2 m16 tiles).
// KV tile = 64 keys, K/V in smem with row stride 36 (conflict-free frag loads).
__global__ __launch_bounds__(128)
void attn_mma() {
    __shared__ __align__(16) float Ks[KT * 36];
    __shared__ __align__(16) float Vs[KT * 36];

    const int tid = threadIdx.x;
    const int w = tid >> 5;
    const int lane = tid & 31;
    const int quad = lane >> 2;
    const int cm = lane & 3;
    const int bh = blockIdx.y;
    const int q0 = blockIdx.x * QT;

    const float* Qb = g_qh + (size_t)bh * LL * DD;
    const float* Kb = g_kh + (size_t)bh * LL * DD;
    const float* Vb = g_vh + (size_t)bh * LL * DD;

    // ---- stage Q tile into Ks(rows 0..63) + Vs(rows 64..127), stride 36 ----
    {
        const float4* Qg = (const float4*)(Qb + (size_t)q0 * DD);
#pragma unroll
        for (int i = 0; i < 8; i++) {
            int g = tid + 128 * i;              // 0..1023
            float4 v = Qg[g];
            int row = g >> 3, c = g & 7;
            float* buf = (row < 64) ? Ks : Vs;
            *(float4*)(buf + (row & 63) * 36 + c * 4) = v;
        }
    }
    __syncthreads();

    // ---- build Q fragments (A of m16n8k8, rows = queries, cols = d) ----
    uint32 qf[2][4][4];
    {
        const float* buf = (w < 2) ? Ks : Vs;
        int rbase = (w & 1) * 32;
#pragma unroll
        for (int mt = 0; mt < 2; mt++) {
            int r = rbase + mt * 16 + quad;
#pragma unroll
            for (int ks = 0; ks < 4; ks++) {
                qf[mt][ks][0] = __float_as_uint(buf[r * 36 + 8 * ks + cm]);
                qf[mt][ks][1] = __float_as_uint(buf[(r + 8) * 36 + 8 * ks + cm]);
                qf[mt][ks][2] = __float_as_uint(buf[r * 36 + 8 * ks + 4 + cm]);
                qf[mt][ks][3] = __float_as_uint(buf[(r + 8) * 36 + 8 * ks + 4 + cm]);
            }
        }
    }
    __syncthreads();

    float O[2][4][4];
#pragma unroll
    for (int mt = 0; mt < 2; mt++)
#pragma unroll
        for (int nd = 0; nd < 4; nd++)
#pragma unroll
            for (int j = 0; j < 4; j++) O[mt][nd][j] = 0.0f;

    float mrow[2][2] = {{-1e30f, -1e30f}, {-1e30f, -1e30f}};
    float lrow[2][2] = {{0.0f, 0.0f}, {0.0f, 0.0f}};

    // prefetch tile 0 into registers
    float4 pk[4], pv[4];
    {
        const float4* Kg = (const float4*)Kb;
        const float4* Vg = (const float4*)Vb;
#pragma unroll
        for (int i = 0; i < 4; i++) {
            pk[i] = Kg[tid + 128 * i];
            pv[i] = Vg[tid + 128 * i];
        }
    }

    const int srcA = (lane & ~3) | (cm >> 1);
    const int srcB = srcA | 2;
    const bool odd = (cm & 1);

    for (int t = 0; t < LL / KT; t++) {
        // store prefetched tile to smem (stride 36)
#pragma unroll
        for (int i = 0; i < 4; i++) {
            int g = tid + 128 * i;
            int row = g >> 3, c = g & 7;
            *(float4*)(Ks + row * 36 + c * 4) = pk[i];
            *(float4*)(Vs + row * 36 + c * 4) = pv[i];
        }
        __syncthreads();

        // issue next tile's global loads (consumed at next iteration's STS)
        if (t + 1 < LL / KT) {
            const float4* Kg = (const float4*)(Kb + (size_t)(t + 1) * KT * DD);
            const float4* Vg = (const float4*)(Vb + (size_t)(t + 1) * KT * DD);
#pragma unroll
            for (int i = 0; i < 4; i++) {
                pk[i] = Kg[tid + 128 * i];
                pv[i] = Vg[tid + 128 * i];
            }
        }

        // ---- S = Q @ K^T (scaled & log2e-folded already) ----
        float S[2][8][4];
#pragma unroll
        for (int mt = 0; mt < 2; mt++)
#pragma unroll
            for (int n = 0; n < 8; n++)
#pragma unroll
                for (int j = 0; j < 4; j++) S[mt][n][j] = 0.0f;

#pragma unroll
        for (int n = 0; n < 8; n++) {
            uint32 bk[4][2];
#pragma unroll
            for (int ks = 0; ks < 4; ks++) {
                const float* kp = Ks + (8 * n + quad) * 36 + 8 * ks + cm;
                bk[ks][0] = __float_as_uint(kp[0]);
                bk[ks][1] = __float_as_uint(kp[4]);
            }
#pragma unroll
            for (int mt = 0; mt < 2; mt++)
#pragma unroll
                for (int ks = 0; ks < 4; ks++)
                    mma_tf32(S[mt][n], qf[mt][ks], bk[ks]);
        }

        // ---- online softmax (base-2) ----
#pragma unroll
        for (int mt = 0; mt < 2; mt++) {
            float t0 = -1e30f, t1 = -1e30f;
#pragma unroll
            for (int n = 0; n < 8; n++) {
                t0 = fmaxf(t0, fmaxf(S[mt][n][0], S[mt][n][1]));
                t1 = fmaxf(t1, fmaxf(S[mt][n][2], S[mt][n][3]));
            }
            t0 = fmaxf(t0, __shfl_xor_sync(0xffffffffu, t0, 1));
            t0 = fmaxf(t0, __shfl_xor_sync(0xffffffffu, t0, 2));
            t1 = fmaxf(t1, __shfl_xor_sync(0xffffffffu, t1, 1));
            t1 = fmaxf(t1, __shfl_xor_sync(0xffffffffu, t1, 2));

            float mn0 = fmaxf(mrow[mt][0], t0);
            float mn1 = fmaxf(mrow[mt][1], t1);
            float c0 = ex2f(mrow[mt][0] - mn0);
            float c1 = ex2f(mrow[mt][1] - mn1);
            mrow[mt][0] = mn0;
            mrow[mt][1] = mn1;
            lrow[mt][0] *= c0;
            lrow[mt][1] *= c1;
#pragma unroll
            for (int nd = 0; nd < 4; nd++) {
                O[mt][nd][0] *= c0;
                O[mt][nd][1] *= c0;
                O[mt][nd][2] *= c1;
                O[mt][nd][3] *= c1;
            }
            float ps0 = 0.0f, ps1 = 0.0f;
#pragma unroll
            for (int n = 0; n < 8; n++) {
                float p0 = ex2f(S[mt][n][0] - mn0);
                float p1 = ex2f(S[mt][n][1] - mn0);
                float p2 = ex2f(S[mt][n][2] - mn1);
                float p3 = ex2f(S[mt][n][3] - mn1);
                ps0 += p0 + p1;
                ps1 += p2 + p3;
                S[mt][n][0] = tf32r(p0);
                S[mt][n][1] = tf32r(p1);
                S[mt][n][2] = tf32r(p2);
                S[mt][n][3] = tf32r(p3);
            }
            lrow[mt][0] += ps0;
            lrow[mt][1] += ps1;
        }

        // ---- O += P @ V : convert C-frags to A-frags via shuffles ----
#pragma unroll
        for (int ks = 0; ks < 8; ks++) {
            uint32 a[2][4];
#pragma unroll
            for (int mt = 0; mt < 2; mt++) {
                float sA0 = __shfl_sync(0xffffffffu, S[mt][ks][0], srcA);
                float sA1 = __shfl_sync(0xffffffffu, S[mt][ks][1], srcA);
                float sA2 = __shfl_sync(0xffffffffu, S[mt][ks][2], srcA);
                float sA3 = __shfl_sync(0xffffffffu, S[mt][ks][3], srcA);
                float sB0 = __shfl_sync(0xffffffffu, S[mt][ks][0], srcB);
                float sB1 = __shfl_sync(0xffffffffu, S[mt][ks][1], srcB);
                float sB2 = __shfl_sync(0xffffffffu, S[mt][ks][2], srcB);
                float sB3 = __shfl_sync(0xffffffffu, S[mt][ks][3], srcB);
                a[mt][0] = __float_as_uint(odd ? sA1 : sA0);
                a[mt][1] = __float_as_uint(odd ? sA3 : sA2);
                a[mt][2] = __float_as_uint(odd ? sB1 : sB0);
                a[mt][3] = __float_as_uint(odd ? sB3 : sB2);
            }
#pragma unroll
            for (int nd = 0; nd < 4; nd++) {
                uint32 bv[2];
                const float* vp0 = Vs + (8 * ks + cm) * 36 + 8 * nd + quad;
                const float* vp1 = Vs + (8 * ks + 4 + cm) * 36 + 8 * nd + quad;
                bv[0] = __float_as_uint(*vp0);
                bv[1] = __float_as_uint(*vp1);
                mma_tf32(O[0][nd], a[0], bv);
                mma_tf32(O[1][nd], a[1], bv);
            }
        }
        __syncthreads();
    }

    // ---- epilogue: normalize and store ----
    float* aob = g_ao + (size_t)bh * LL * DD;
#pragma unroll
    for (int mt = 0; mt < 2; mt++) {
        float l0 = lrow[mt][0], l1 = lrow[mt][1];
        l0 += __shfl_xor_sync(0xffffffffu, l0, 1);
        l0 += __shfl_xor_sync(0xffffffffu, l0, 2);
        l1 += __shfl_xor_sync(0xffffffffu, l1, 1);
        l1 += __shfl_xor_sync(0xffffffffu, l1, 2);
        float i0 = 1.0f / l0, i1 = 1.0f / l1;
        int qrow = q0 + w * 32 + mt * 16 + quad;
#pragma unroll
        for (int nd = 0; nd < 4; nd++) {
            float2 v0 = make_float2(O[mt][nd][0] * i0, O[mt][nd][1] * i0);
            float2 v1 = make_float2(O[mt][nd][2] * i1, O[mt][nd][3] * i1);
            *(float2*)(aob + (size_t)qrow * DD + 8 * nd + 2 * cm) = v0;
            *(float2*)(aob + (size_t)(qrow + 8) * DD + 8 * nd + 2 * cm) = v1;
        }
    }
}

// ---------------- launcher ----------------
extern "C" void kernel_launch(void* const* d_in, const int* in_sizes, int n_in,
                              void* d_out, int out_size) {
    const float* q  = (const float*)d_in[0];
    const float* k  = (const float*)d_in[1];
    const float* v  = (const float*)d_in[2];
    const float* Wq = (const float*)d_in[3];
    const float* bq = (const float*)d_in[4];
    const float* Wk = (const float*)d_in[5];
    const float* bk = (const float*)d_in[6];
    const float* Wv = (const float*)d_in[7];
    const float* bv = (const float*)d_in[8];
    const float* Wo = (const float*)d_in[9];
    const float* bo = (const float*)d_in[10];
    float* out = (float*)d_out;

    rope_table_kernel<<<(LL * NPAIR + 255) / 256, 256>>>();

    dim3 gg(EE / 64, (BB * LL) / 64);
    gemm_proj<0><<<gg, 256>>>(q, Wq, bq, nullptr);
    gemm_proj<1><<<gg, 256>>>(k, Wk, bk, nullptr);
    gemm_proj<2><<<gg, 256>>>(v, Wv, bv, nullptr);

    attn_mma<<<dim3(LL / QT, BB * HH), 128>>>();

    gemm_proj<3><<<gg, 256>>>(nullptr, Wo, bo, out);
}

// round 3
// speedup vs baseline: 4.1800x; 1.2221x over previous
#include <cuda_runtime.h>
#include <cuda_bf16.h>
#include <math.h>

// Problem constants
#define BB 2
#define LL 4096
#define EE 256
#define HH 8
#define DD 32
#define NPAIR 16
#define KT 64     // keys per attention tile
#define QT 128    // queries per attention CTA

typedef unsigned int uint32;

// ---------------- device scratch ----------------
__device__ float g_qh[BB*HH*LL*DD];
__device__ float g_kh[BB*HH*LL*DD];
__device__ float g_vh[BB*HH*LL*DD];
__device__ float g_ao[BB*HH*LL*DD];
__device__ float g_cos[LL*NPAIR];
__device__ float g_sin[LL*NPAIR];

// ---------------- helpers ----------------
__device__ __forceinline__ float tf32r(float x) {
    uint32 u;
    asm("cvt.rna.tf32.f32 %0, %1;" : "=r"(u) : "f"(x));
    return __uint_as_float(u);
}
__device__ __forceinline__ void split32(float x, uint32& hi, uint32& lo) {
    uint32 h;
    asm("cvt.rna.tf32.f32 %0, %1;" : "=r"(h) : "f"(x));
    float r = x - __uint_as_float(h);
    uint32 l;
    asm("cvt.rna.tf32.f32 %0, %1;" : "=r"(l) : "f"(r));
    hi = h; lo = l;
}
__device__ __forceinline__ float ex2f(float x) {
    float r;
    asm("ex2.approx.f32 %0, %1;" : "=f"(r) : "f"(x));
    return r;
}
__device__ __forceinline__ void mma_tf32(float* d, const uint32* a, const uint32* b) {
    asm volatile(
        "mma.sync.aligned.m16n8k8.row.col.f32.tf32.tf32.f32 "
        "{%0,%1,%2,%3}, {%4,%5,%6,%7}, {%8,%9}, {%0,%1,%2,%3};"
        : "+f"(d[0]), "+f"(d[1]), "+f"(d[2]), "+f"(d[3])
        : "r"(a[0]), "r"(a[1]), "r"(a[2]), "r"(a[3]), "r"(b[0]), "r"(b[1]));
}

// ---------------- rope table ----------------
__global__ void rope_table_kernel() {
    int idx = blockIdx.x * blockDim.x + threadIdx.x;
    if (idx >= LL * NPAIR) return;
    int l = idx >> 4;
    int i = idx & 15;
    float t = (i < 8) ? (float)(l & 63) : (float)(l >> 6);
    int fi = i & 7;
    float freq = powf(10000.0f, -(4.0f * (float)fi) / 32.0f);
    float ang = t * freq;
    g_cos[idx] = cosf(ang);
    g_sin[idx] = sinf(ang);
}

// ---------------- tensor-core projection GEMM (tf32x3, fp32-accurate) ----
// C[M=8192, N=256] = A[M,256] @ W[N,256]^T + bias
// MODE 0: Q proj -> rope -> *scale*log2e -> tf32 round -> g_qh
// MODE 1: K proj -> rope -> tf32 round -> g_kh
// MODE 2: V proj -> tf32 round -> g_vh
// MODE 3: out proj (A gathered from g_ao) -> d_out
// CTA: 128 threads = 4 warps in 2x2; CTA tile 64(M)x64(N); warp tile 32x32.
template <int MODE>
__global__ __launch_bounds__(128)
void gemm_mma(const float* __restrict__ A, const float* __restrict__ W,
              const float* __restrict__ bias, float* __restrict__ out) {
    __shared__ __align__(16) float As[64 * 36];
    __shared__ __align__(16) float Ws[64 * 36];

    const int tid = threadIdx.x;
    const int w = tid >> 5, lane = tid & 31;
    const int quad = lane >> 2, cm = lane & 3;
    const int wm = w >> 1, wn = w & 1;
    const int m0 = blockIdx.y * 64;
    const int n0 = blockIdx.x * 64;

    float C[2][4][4];
#pragma unroll
    for (int mt = 0; mt < 2; mt++)
#pragma unroll
        for (int nt = 0; nt < 4; nt++)
#pragma unroll
            for (int j = 0; j < 4; j++) C[mt][nt][j] = 0.0f;

    float4 pa[4], pw[4];
    // prefetch chunk 0
#pragma unroll
    for (int i = 0; i < 4; i++) {
        int g = tid + 128 * i;
        int row = g >> 3, c4 = g & 7;
        if (MODE != 3) {
            pa[i] = *(const float4*)(A + (size_t)(m0 + row) * 256 + c4 * 4);
        } else {
            int m = m0 + row;
            int b = m >> 12, l = m & 4095;
            pa[i] = *(const float4*)(g_ao + (((size_t)(b * 8 + 0) * 4096) + l) * 32 + c4 * 4);
        }
        pw[i] = *(const float4*)(W + (size_t)(n0 + row) * 256 + c4 * 4);
    }

    for (int ch = 0; ch < 8; ch++) {
#pragma unroll
        for (int i = 0; i < 4; i++) {
            int g = tid + 128 * i;
            int row = g >> 3, c4 = g & 7;
            *(float4*)(As + row * 36 + c4 * 4) = pa[i];
            *(float4*)(Ws + row * 36 + c4 * 4) = pw[i];
        }
        __syncthreads();

        if (ch < 7) {
            int kc = (ch + 1) * 32;
#pragma unroll
            for (int i = 0; i < 4; i++) {
                int g = tid + 128 * i;
                int row = g >> 3, c4 = g & 7;
                if (MODE != 3) {
                    pa[i] = *(const float4*)(A + (size_t)(m0 + row) * 256 + kc + c4 * 4);
                } else {
                    int m = m0 + row;
                    int b = m >> 12, l = m & 4095;
                    pa[i] = *(const float4*)(g_ao + (((size_t)(b * 8 + ch + 1) * 4096) + l) * 32 + c4 * 4);
                }
                pw[i] = *(const float4*)(W + (size_t)(n0 + row) * 256 + kc + c4 * 4);
            }
        }

#pragma unroll
        for (int ks = 0; ks < 4; ks++) {
            uint32 ah[2][4], al[2][4];
#pragma unroll
            for (int mt = 0; mt < 2; mt++) {
                int r = wm * 32 + mt * 16 + quad;
                float x0 = As[r * 36 + ks * 8 + cm];
                float x1 = As[(r + 8) * 36 + ks * 8 + cm];
                float x2 = As[r * 36 + ks * 8 + 4 + cm];
                float x3 = As[(r + 8) * 36 + ks * 8 + 4 + cm];
                split32(x0, ah[mt][0], al[mt][0]);
                split32(x1, ah[mt][1], al[mt][1]);
                split32(x2, ah[mt][2], al[mt][2]);
                split32(x3, ah[mt][3], al[mt][3]);
            }
            uint32 bh[4][2], bl[4][2];
#pragma unroll
            for (int nt = 0; nt < 4; nt++) {
                int r = wn * 32 + nt * 8 + quad;
                float y0 = Ws[r * 36 + ks * 8 + cm];
                float y1 = Ws[r * 36 + ks * 8 + 4 + cm];
                split32(y0, bh[nt][0], bl[nt][0]);
                split32(y1, bh[nt][1], bl[nt][1]);
            }
#pragma unroll
            for (int mt = 0; mt < 2; mt++)
#pragma unroll
                for (int nt = 0; nt < 4; nt++) {
                    mma_tf32(C[mt][nt], ah[mt], bh[nt]);
                    mma_tf32(C[mt][nt], al[mt], bh[nt]);
                    mma_tf32(C[mt][nt], ah[mt], bl[nt]);
                }
        }
        __syncthreads();
    }

    // ---- epilogue ----
    const float QS = 0.17677669529663687f * 1.4426950408889634f;
#pragma unroll
    for (int mt = 0; mt < 2; mt++) {
        int row0 = m0 + wm * 32 + mt * 16 + quad;
#pragma unroll
        for (int nt = 0; nt < 4; nt++) {
            int col = n0 + wn * 32 + nt * 8 + 2 * cm;
            float b0 = bias[col], b1 = bias[col + 1];
#pragma unroll
            for (int half = 0; half < 2; half++) {
                int row = row0 + half * 8;
                float real = C[mt][nt][half * 2 + 0] + b0;
                float imag = C[mt][nt][half * 2 + 1] + b1;
                if (MODE == 3) {
                    *(float2*)(out + (size_t)row * 256 + col) = make_float2(real, imag);
                } else {
                    int l = row & 4095, b = row >> 12;
                    int h = col >> 5, d = col & 31;
                    float out_r = real, out_i = imag;
                    if (MODE != 2) {
                        int p = d >> 1;
                        float cs = g_cos[l * NPAIR + p];
                        float sn = g_sin[l * NPAIR + p];
                        out_r = real * cs - imag * sn;
                        out_i = real * sn + imag * cs;
                        if (MODE == 0) { out_r *= QS; out_i *= QS; }
                    }
                    out_r = tf32r(out_r);
                    out_i = tf32r(out_i);
                    float* dst = (MODE == 0) ? g_qh : (MODE == 1) ? g_kh : g_vh;
                    *(float2*)(dst + (((size_t)(b * 8 + h) * 4096) + l) * 32 + d) =
                        make_float2(out_r, out_i);
                }
            }
        }
    }
}

// ---------------- flash attention with tf32 mma.sync ----------------
__global__ __launch_bounds__(128)
void attn_mma() {
    __shared__ __align__(16) float Ks[KT * 36];
    __shared__ __align__(16) float Vs[KT * 36];

    const int tid = threadIdx.x;
    const int w = tid >> 5;
    const int lane = tid & 31;
    const int quad = lane >> 2;
    const int cm = lane & 3;
    const int bh = blockIdx.y;
    const int q0 = blockIdx.x * QT;

    const float* Qb = g_qh + (size_t)bh * LL * DD;
    const float* Kb = g_kh + (size_t)bh * LL * DD;
    const float* Vb = g_vh + (size_t)bh * LL * DD;

    // ---- stage Q tile ----
    {
        const float4* Qg = (const float4*)(Qb + (size_t)q0 * DD);
#pragma unroll
        for (int i = 0; i < 8; i++) {
            int g = tid + 128 * i;
            float4 v = Qg[g];
            int row = g >> 3, c = g & 7;
            float* buf = (row < 64) ? Ks : Vs;
            *(float4*)(buf + (row & 63) * 36 + c * 4) = v;
        }
    }
    __syncthreads();

    uint32 qf[2][4][4];
    {
        const float* buf = (w < 2) ? Ks : Vs;
        int rbase = (w & 1) * 32;
#pragma unroll
        for (int mt = 0; mt < 2; mt++) {
            int r = rbase + mt * 16 + quad;
#pragma unroll
            for (int ks = 0; ks < 4; ks++) {
                qf[mt][ks][0] = __float_as_uint(buf[r * 36 + 8 * ks + cm]);
                qf[mt][ks][1] = __float_as_uint(buf[(r + 8) * 36 + 8 * ks + cm]);
                qf[mt][ks][2] = __float_as_uint(buf[r * 36 + 8 * ks + 4 + cm]);
                qf[mt][ks][3] = __float_as_uint(buf[(r + 8) * 36 + 8 * ks + 4 + cm]);
            }
        }
    }
    __syncthreads();

    float O[2][4][4];
#pragma unroll
    for (int mt = 0; mt < 2; mt++)
#pragma unroll
        for (int nd = 0; nd < 4; nd++)
#pragma unroll
            for (int j = 0; j < 4; j++) O[mt][nd][j] = 0.0f;

    float mrow[2][2] = {{-1e30f, -1e30f}, {-1e30f, -1e30f}};
    float lrow[2][2] = {{0.0f, 0.0f}, {0.0f, 0.0f}};

    float4 pk[4], pv[4];
    {
        const float4* Kg = (const float4*)Kb;
        const float4* Vg = (const float4*)Vb;
#pragma unroll
        for (int i = 0; i < 4; i++) {
            pk[i] = Kg[tid + 128 * i];
            pv[i] = Vg[tid + 128 * i];
        }
    }

    const int srcA = (lane & ~3) | (cm >> 1);
    const int srcB = srcA | 2;
    const bool odd = (cm & 1);

    for (int t = 0; t < LL / KT; t++) {
#pragma unroll
        for (int i = 0; i < 4; i++) {
            int g = tid + 128 * i;
            int row = g >> 3, c = g & 7;
            *(float4*)(Ks + row * 36 + c * 4) = pk[i];
            *(float4*)(Vs + row * 36 + c * 4) = pv[i];
        }
        __syncthreads();

        if (t + 1 < LL / KT) {
            const float4* Kg = (const float4*)(Kb + (size_t)(t + 1) * KT * DD);
            const float4* Vg = (const float4*)(Vb + (size_t)(t + 1) * KT * DD);
#pragma unroll
            for (int i = 0; i < 4; i++) {
                pk[i] = Kg[tid + 128 * i];
                pv[i] = Vg[tid + 128 * i];
            }
        }

        float S[2][8][4];
#pragma unroll
        for (int mt = 0; mt < 2; mt++)
#pragma unroll
            for (int n = 0; n < 8; n++)
#pragma unroll
                for (int j = 0; j < 4; j++) S[mt][n][j] = 0.0f;

#pragma unroll
        for (int n = 0; n < 8; n++) {
            uint32 bk[4][2];
#pragma unroll
            for (int ks = 0; ks < 4; ks++) {
                const float* kp = Ks + (8 * n + quad) * 36 + 8 * ks + cm;
                bk[ks][0] = __float_as_uint(kp[0]);
                bk[ks][1] = __float_as_uint(kp[4]);
            }
#pragma unroll
            for (int mt = 0; mt < 2; mt++)
#pragma unroll
                for (int ks = 0; ks < 4; ks++)
                    mma_tf32(S[mt][n], qf[mt][ks], bk[ks]);
        }

#pragma unroll
        for (int mt = 0; mt < 2; mt++) {
            float t0 = -1e30f, t1 = -1e30f;
#pragma unroll
            for (int n = 0; n < 8; n++) {
                t0 = fmaxf(t0, fmaxf(S[mt][n][0], S[mt][n][1]));
                t1 = fmaxf(t1, fmaxf(S[mt][n][2], S[mt][n][3]));
            }
            t0 = fmaxf(t0, __shfl_xor_sync(0xffffffffu, t0, 1));
            t0 = fmaxf(t0, __shfl_xor_sync(0xffffffffu, t0, 2));
            t1 = fmaxf(t1, __shfl_xor_sync(0xffffffffu, t1, 1));
            t1 = fmaxf(t1, __shfl_xor_sync(0xffffffffu, t1, 2));

            float mn0 = fmaxf(mrow[mt][0], t0);
            float mn1 = fmaxf(mrow[mt][1], t1);
            float c0 = ex2f(mrow[mt][0] - mn0);
            float c1 = ex2f(mrow[mt][1] - mn1);
            mrow[mt][0] = mn0;
            mrow[mt][1] = mn1;
            lrow[mt][0] *= c0;
            lrow[mt][1] *= c1;
#pragma unroll
            for (int nd = 0; nd < 4; nd++) {
                O[mt][nd][0] *= c0;
                O[mt][nd][1] *= c0;
                O[mt][nd][2] *= c1;
                O[mt][nd][3] *= c1;
            }
            float ps0 = 0.0f, ps1 = 0.0f;
#pragma unroll
            for (int n = 0; n < 8; n++) {
                float p0 = ex2f(S[mt][n][0] - mn0);
                float p1 = ex2f(S[mt][n][1] - mn0);
                float p2 = ex2f(S[mt][n][2] - mn1);
                float p3 = ex2f(S[mt][n][3] - mn1);
                ps0 += p0 + p1;
                ps1 += p2 + p3;
                S[mt][n][0] = p0;
                S[mt][n][1] = p1;
                S[mt][n][2] = p2;
                S[mt][n][3] = p3;
            }
            lrow[mt][0] += ps0;
            lrow[mt][1] += ps1;
        }

#pragma unroll
        for (int ks = 0; ks < 8; ks++) {
            uint32 a[2][4];
#pragma unroll
            for (int mt = 0; mt < 2; mt++) {
                float sA0 = __shfl_sync(0xffffffffu, S[mt][ks][0], srcA);
                float sA1 = __shfl_sync(0xffffffffu, S[mt][ks][1], srcA);
                float sA2 = __shfl_sync(0xffffffffu, S[mt][ks][2], srcA);
                float sA3 = __shfl_sync(0xffffffffu, S[mt][ks][3], srcA);
                float sB0 = __shfl_sync(0xffffffffu, S[mt][ks][0], srcB);
                float sB1 = __shfl_sync(0xffffffffu, S[mt][ks][1], srcB);
                float sB2 = __shfl_sync(0xffffffffu, S[mt][ks][2], srcB);
                float sB3 = __shfl_sync(0xffffffffu, S[mt][ks][3], srcB);
                a[mt][0] = __float_as_uint(odd ? sA1 : sA0);
                a[mt][1] = __float_as_uint(odd ? sA3 : sA2);
                a[mt][2] = __float_as_uint(odd ? sB1 : sB0);
                a[mt][3] = __float_as_uint(odd ? sB3 : sB2);
            }
#pragma unroll
            for (int nd = 0; nd < 4; nd++) {
                uint32 bv[2];
                const float* vp0 = Vs + (8 * ks + cm) * 36 + 8 * nd + quad;
                const float* vp1 = Vs + (8 * ks + 4 + cm) * 36 + 8 * nd + quad;
                bv[0] = __float_as_uint(*vp0);
                bv[1] = __float_as_uint(*vp1);
                mma_tf32(O[0][nd], a[0], bv);
                mma_tf32(O[1][nd], a[1], bv);
            }
        }
        __syncthreads();
    }

    float* aob = g_ao + (size_t)bh * LL * DD;
#pragma unroll
    for (int mt = 0; mt < 2; mt++) {
        float l0 = lrow[mt][0], l1 = lrow[mt][1];
        l0 += __shfl_xor_sync(0xffffffffu, l0, 1);
        l0 += __shfl_xor_sync(0xffffffffu, l0, 2);
        l1 += __shfl_xor_sync(0xffffffffu, l1, 1);
        l1 += __shfl_xor_sync(0xffffffffu, l1, 2);
        float i0 = 1.0f / l0, i1 = 1.0f / l1;
        int qrow = q0 + w * 32 + mt * 16 + quad;
#pragma unroll
        for (int nd = 0; nd < 4; nd++) {
            float2 v0 = make_float2(O[mt][nd][0] * i0, O[mt][nd][1] * i0);
            float2 v1 = make_float2(O[mt][nd][2] * i1, O[mt][nd][3] * i1);
            *(float2*)(aob + (size_t)qrow * DD + 8 * nd + 2 * cm) = v0;
            *(float2*)(aob + (size_t)(qrow + 8) * DD + 8 * nd + 2 * cm) = v1;
        }
    }
}

// ---------------- launcher ----------------
extern "C" void kernel_launch(void* const* d_in, const int* in_sizes, int n_in,
                              void* d_out, int out_size) {
    const float* q  = (const float*)d_in[0];
    const float* k  = (const float*)d_in[1];
    const float* v  = (const float*)d_in[2];
    const float* Wq = (const float*)d_in[3];
    const float* bq = (const float*)d_in[4];
    const float* Wk = (const float*)d_in[5];
    const float* bk = (const float*)d_in[6];
    const float* Wv = (const float*)d_in[7];
    const float* bv = (const float*)d_in[8];
    const float* Wo = (const float*)d_in[9];
    const float* bo = (const float*)d_in[10];
    float* out = (float*)d_out;

    rope_table_kernel<<<(LL * NPAIR + 255) / 256, 256>>>();

    dim3 gg(EE / 64, (BB * LL) / 64);  // (4, 128)
    gemm_mma<0><<<gg, 128>>>(q, Wq, bq, nullptr);
    gemm_mma<1><<<gg, 128>>>(k, Wk, bk, nullptr);
    gemm_mma<2><<<gg, 128>>>(v, Wv, bv, nullptr);

    attn_mma<<<dim3(LL / QT, BB * HH), 128>>>();

    gemm_mma<3><<<gg, 128>>>(nullptr, Wo, bo, out);
}